// round 2
// baseline (speedup 1.0000x reference)
#include <cuda_runtime.h>
#include <math.h>

#define NB 64
#define N 1024
#define ITERS 10
#define G 16              // batches per L2-resident group
#define NGROUPS (NB / G)

// Scratch potentials (allocation-free): u[b][i], v[b][j]
__device__ __align__(16) float g_u[NB * N];
__device__ __align__(16) float g_v[NB * N];

__device__ __forceinline__ float clampA(float m) {
    // clip(M, -25, 25) / 0.1
    return fminf(fmaxf(m, -25.0f), 25.0f) * 10.0f;
}

// Branch-form online LSE update: 1 expf in the common (no-new-max) path.
__device__ __forceinline__ void lse_upd(float x, float& m, float& s) {
    if (x <= m) {
        s += __expf(x - m);
    } else {
        s = s * __expf(m - x) + 1.0f;
        m = x;
    }
}

__global__ void init_v_kernel() {
    int t = blockIdx.x * blockDim.x + threadIdx.x;
    if (t < NB * N) g_v[t] = 0.0f;
}

// u[b][i] = LSE_j( A[b][i][j] - v[b][j] ), one warp per row. Group offset b0.
__global__ void __launch_bounds__(256) row_lse_kernel(const float* __restrict__ M, int b0) {
    int warp = (blockIdx.x * 256 + threadIdx.x) >> 5;   // row id within group
    int lane = threadIdx.x & 31;
    int b = b0 + (warp >> 10);
    int i = warp & (N - 1);

    const float4* __restrict__ row4 = reinterpret_cast<const float4*>(M + ((size_t)b * N + i) * N);
    const float4* __restrict__ v4   = reinterpret_cast<const float4*>(g_v + b * N);

    float x[32];
    float mx = -1e30f;
#pragma unroll
    for (int k = 0; k < 8; k++) {
        int idx = lane + 32 * k;
        float4 a = row4[idx];
        float4 v = v4[idx];
        float x0 = clampA(a.x) - v.x;
        float x1 = clampA(a.y) - v.y;
        float x2 = clampA(a.z) - v.z;
        float x3 = clampA(a.w) - v.w;
        x[4 * k + 0] = x0; x[4 * k + 1] = x1;
        x[4 * k + 2] = x2; x[4 * k + 3] = x3;
        mx = fmaxf(mx, fmaxf(fmaxf(x0, x1), fmaxf(x2, x3)));
    }
#pragma unroll
    for (int o = 16; o > 0; o >>= 1)
        mx = fmaxf(mx, __shfl_xor_sync(0xFFFFFFFFu, mx, o));

    float s = 0.0f;
#pragma unroll
    for (int k = 0; k < 32; k++)
        s += __expf(x[k] - mx);
#pragma unroll
    for (int o = 16; o > 0; o >>= 1)
        s += __shfl_xor_sync(0xFFFFFFFFu, s, o);

    if (lane == 0)
        g_u[b * N + i] = mx + __logf(s);
}

// v[b][j] = LSE_i( A[b][i][j] - u[b][i] ).
// Block: (64 cols, 16 row-groups) = 1024 threads. Grid: (N/64, G).
// Thread (x,y) covers column j, rows {y, y+16, y+32, ...} (64 rows),
// then 16 partial (m,s) pairs per column are merged in shared memory.
__global__ void __launch_bounds__(1024) col_lse_kernel(const float* __restrict__ M, int b0) {
    int b = b0 + blockIdx.y;
    int x = threadIdx.x;            // 0..63
    int y = threadIdx.y;            // 0..15
    int j = blockIdx.x * 64 + x;

    __shared__ float us[N];
    __shared__ float sm_m[16][65];
    __shared__ float sm_s[16][65];

    {
        int t = y * 64 + x;
        // 1024 threads load 1024 u values
        us[t] = g_u[b * N + t];
    }
    __syncthreads();

    const float* __restrict__ base = M + (size_t)b * N * N + j;

    float m = -1e30f, s = 0.0f;

#pragma unroll 4
    for (int k = 0; k < N / 16; k++) {
        int i = y + 16 * k;
        float a = base[(size_t)i * N];
        float xv = clampA(a) - us[i];
        lse_upd(xv, m, s);
    }

    sm_m[y][x] = m;
    sm_s[y][x] = s;
    __syncthreads();

    if (y == 0) {
        float mm = sm_m[0][x], ss = sm_s[0][x];
#pragma unroll
        for (int k = 1; k < 16; k++) {
            float mk = sm_m[k][x], sk = sm_s[k][x];
            if (mk <= mm) {
                ss += sk * __expf(mk - mm);
            } else {
                ss = ss * __expf(mm - mk) + sk;
                mm = mk;
            }
        }
        g_v[b * N + j] = mm + __logf(ss);
    }
}

// out = exp(A - u_i - v_j), float4-vectorized, per group.
__global__ void __launch_bounds__(256) finalize_kernel(const float* __restrict__ M,
                                                       float* __restrict__ out, int b0) {
    size_t t0 = (size_t)b0 * N * (N / 4);
    size_t t = t0 + (size_t)blockIdx.x * 256 + threadIdx.x;  // global float4 index
    int j4 = (int)(t & 255);          // 256 float4 per row
    size_t r = t >> 8;                // global row id
    int b = (int)(r >> 10);

    float u = g_u[r];
    float4 v = reinterpret_cast<const float4*>(g_v + b * N)[j4];
    float4 a = reinterpret_cast<const float4*>(M)[t];

    float4 o;
    o.x = __expf(clampA(a.x) - u - v.x);
    o.y = __expf(clampA(a.y) - u - v.y);
    o.z = __expf(clampA(a.z) - u - v.z);
    o.w = __expf(clampA(a.w) - u - v.w);
    reinterpret_cast<float4*>(out)[t] = o;
}

extern "C" void kernel_launch(void* const* d_in, const int* in_sizes, int n_in,
                              void* d_out, int out_size) {
    const float* M = (const float*)d_in[0];
    float* out = (float*)d_out;

    init_v_kernel<<<(NB * N + 255) / 256, 256>>>();

    for (int g = 0; g < NGROUPS; g++) {
        int b0 = g * G;
        for (int it = 0; it < ITERS; it++) {
            // G*1024 rows, 8 warps/block
            row_lse_kernel<<<(G * N) / 8, 256>>>(M, b0);
            // (N/64) col tiles x G batches, 1024 threads
            col_lse_kernel<<<dim3(N / 64, G), dim3(64, 16)>>>(M, b0);
        }
        // G*1024*1024/4 float4s, 256 threads/block
        finalize_kernel<<<(G * N * (N / 4)) / 256, 256>>>(M, out, b0);
    }
}

// round 3
// speedup vs baseline: 1.5543x; 1.5543x over previous
#include <cuda_runtime.h>
#include <math.h>

#define NB 64
#define N 1024
#define ITERS 10

// Scratch potentials (allocation-free): u[b][i], v[b][j]
__device__ __align__(16) float g_u[NB * N];
__device__ __align__(16) float g_v[NB * N];

__device__ __forceinline__ float clampA(float m) {
    // clip(M, -25, 25) / 0.1
    return fminf(fmaxf(m, -25.0f), 25.0f) * 10.0f;
}

__global__ void init_v_kernel() {
    int t = blockIdx.x * blockDim.x + threadIdx.x;
    if (t < NB * N) g_v[t] = 0.0f;
}

// u[b][i] = LSE_j( A[b][i][j] - v[b][j] ), one warp per row.
__global__ void __launch_bounds__(256) row_lse_kernel(const float* __restrict__ M) {
    int warp = (blockIdx.x * 256 + threadIdx.x) >> 5;   // global row id, 0..65535
    int lane = threadIdx.x & 31;
    int b = warp >> 10;
    int i = warp & (N - 1);

    const float4* __restrict__ row4 = reinterpret_cast<const float4*>(M + ((size_t)b * N + i) * N);
    const float4* __restrict__ v4   = reinterpret_cast<const float4*>(g_v + b * N);

    float x[32];
    float mx = -1e30f;
#pragma unroll
    for (int k = 0; k < 8; k++) {
        int idx = lane + 32 * k;
        float4 a = row4[idx];
        float4 v = v4[idx];
        float x0 = clampA(a.x) - v.x;
        float x1 = clampA(a.y) - v.y;
        float x2 = clampA(a.z) - v.z;
        float x3 = clampA(a.w) - v.w;
        x[4 * k + 0] = x0; x[4 * k + 1] = x1;
        x[4 * k + 2] = x2; x[4 * k + 3] = x3;
        mx = fmaxf(mx, fmaxf(fmaxf(x0, x1), fmaxf(x2, x3)));
    }
#pragma unroll
    for (int o = 16; o > 0; o >>= 1)
        mx = fmaxf(mx, __shfl_xor_sync(0xFFFFFFFFu, mx, o));

    float s = 0.0f;
#pragma unroll
    for (int k = 0; k < 32; k++)
        s += __expf(x[k] - mx);
#pragma unroll
    for (int o = 16; o > 0; o >>= 1)
        s += __shfl_xor_sync(0xFFFFFFFFu, s, o);

    if (lane == 0)
        g_u[b * N + i] = mx + __logf(s);
}

// v[b][j] = LSE_i( A[b][i][j] - u[b][i] ).
// Block: (32 cols, 32 row-groups) = 1024 threads. Grid: (N/32, NB).
// Thread (x,y) holds rows {y, y+32, ...} (32 values) of column j in registers,
// computes the block-wide column max via shared, then one independent expf per
// element (no serial online-LSE chain).
__global__ void __launch_bounds__(1024) col_lse_kernel(const float* __restrict__ M) {
    int b = blockIdx.y;
    int cx = threadIdx.x;           // 0..31 (column within tile)
    int y  = threadIdx.y;           // 0..31 (row-group)
    int j = blockIdx.x * 32 + cx;

    __shared__ float us[N];
    __shared__ float sm_m[32][33];
    __shared__ float sm_s[32][33];

    us[y * 32 + cx] = g_u[b * N + y * 32 + cx];
    __syncthreads();

    const float* __restrict__ base = M + (size_t)b * N * N + j;

    float xv[32];
    float mx = -1e30f;
#pragma unroll
    for (int k = 0; k < 32; k++) {
        int i = y + 32 * k;
        float a = base[(size_t)i * N];
        float t = clampA(a) - us[i];
        xv[k] = t;
        mx = fmaxf(mx, t);
    }

    sm_m[y][cx] = mx;
    __syncthreads();

    // Column max across the 32 row-group partials (redundant per thread, cheap LDS)
    float MX = sm_m[0][cx];
#pragma unroll
    for (int k = 1; k < 32; k++)
        MX = fmaxf(MX, sm_m[k][cx]);

    float s = 0.0f;
#pragma unroll
    for (int k = 0; k < 32; k++)
        s += __expf(xv[k] - MX);

    sm_s[y][cx] = s;
    __syncthreads();

    if (y == 0) {
        float SS = sm_s[0][cx];
#pragma unroll
        for (int k = 1; k < 32; k++)
            SS += sm_s[k][cx];
        g_v[b * N + j] = MX + __logf(SS);
    }
}

// Last col pass fused with output: computes v_j, then writes exp(x - v_j)
// directly from the register-resident values. Saves one full 256MB read.
__global__ void __launch_bounds__(1024) col_lse_finalize_kernel(const float* __restrict__ M,
                                                                float* __restrict__ out) {
    int b = blockIdx.y;
    int cx = threadIdx.x;
    int y  = threadIdx.y;
    int j = blockIdx.x * 32 + cx;

    __shared__ float us[N];
    __shared__ float sm_m[32][33];
    __shared__ float sm_s[32][33];

    us[y * 32 + cx] = g_u[b * N + y * 32 + cx];
    __syncthreads();

    const float* __restrict__ base = M + (size_t)b * N * N + j;

    float xv[32];
    float mx = -1e30f;
#pragma unroll
    for (int k = 0; k < 32; k++) {
        int i = y + 32 * k;
        float a = base[(size_t)i * N];
        float t = clampA(a) - us[i];
        xv[k] = t;
        mx = fmaxf(mx, t);
    }

    sm_m[y][cx] = mx;
    __syncthreads();

    float MX = sm_m[0][cx];
#pragma unroll
    for (int k = 1; k < 32; k++)
        MX = fmaxf(MX, sm_m[k][cx]);

    float s = 0.0f;
#pragma unroll
    for (int k = 0; k < 32; k++)
        s += __expf(xv[k] - MX);

    sm_s[y][cx] = s;
    __syncthreads();

    // All threads need v_j: compute the column sum redundantly.
    float SS = sm_s[0][cx];
#pragma unroll
    for (int k = 1; k < 32; k++)
        SS += sm_s[k][cx];
    float V = MX + __logf(SS);   // v_j (relative shift already in MX)

    float* __restrict__ obase = out + (size_t)b * N * N + j;
#pragma unroll
    for (int k = 0; k < 32; k++) {
        int i = y + 32 * k;
        obase[(size_t)i * N] = __expf(xv[k] - V);
    }
}

extern "C" void kernel_launch(void* const* d_in, const int* in_sizes, int n_in,
                              void* d_out, int out_size) {
    const float* M = (const float*)d_in[0];
    float* out = (float*)d_out;

    init_v_kernel<<<(NB * N + 255) / 256, 256>>>();

    for (int it = 0; it < ITERS; it++) {
        // 64*1024 rows, 8 warps/block
        row_lse_kernel<<<(NB * N) / 8, 256>>>(M);
        if (it < ITERS - 1) {
            col_lse_kernel<<<dim3(N / 32, NB), dim3(32, 32)>>>(M);
        } else {
            col_lse_finalize_kernel<<<dim3(N / 32, NB), dim3(32, 32)>>>(M, out);
        }
    }
}

// round 4
// speedup vs baseline: 1.9435x; 1.2504x over previous
#include <cuda_runtime.h>
#include <math.h>

#define NB 64
#define N 1024
#define ITERS 10

// Scratch (allocation-free)
__device__ __align__(16) float g_u[NB * N];
__device__ __align__(16) float g_v[NB * N];
// Col-pass partials: [batch][chunk][col], 8 row-chunks of 128 rows
#define NCHUNK 8
__device__ __align__(16) float g_pm[NB * NCHUNK * N];
__device__ __align__(16) float g_ps[NB * NCHUNK * N];

__device__ __forceinline__ float clampA(float m) {
    return fminf(fmaxf(m, -25.0f), 25.0f) * 10.0f;   // clip(M,±25)/0.1
}

__global__ void init_v_kernel() {
    int t = blockIdx.x * blockDim.x + threadIdx.x;
    if (t < NB * N) g_v[t] = 0.0f;
}

// ---------------------------------------------------------------------------
// Row pass: u[b][i] = LSE_j( A[b][i][j] - v[b][j] ). Two warps per row.
// Block 256 = 4 rows x 64 threads. Each thread holds 16 values (4 float4s).
// ---------------------------------------------------------------------------
__global__ void __launch_bounds__(256) row_lse_kernel(const float* __restrict__ M) {
    int rl   = threadIdx.x >> 6;        // 0..3 row within block
    int tr   = threadIdx.x & 63;        // thread within row
    int half = tr >> 5;
    int lane = tr & 31;
    size_t r = (size_t)blockIdx.x * 4 + rl;     // global row id
    int b = (int)(r >> 10);

    const float4* __restrict__ row4 = reinterpret_cast<const float4*>(M) + r * (N / 4);
    const float4* __restrict__ v4   = reinterpret_cast<const float4*>(g_v + b * N);

    float x[16];
    float mx = -1e30f;
#pragma unroll
    for (int k = 0; k < 4; k++) {
        int idx = tr + 64 * k;
        float4 a = row4[idx];
        float4 v = v4[idx];
        float x0 = clampA(a.x) - v.x;
        float x1 = clampA(a.y) - v.y;
        float x2 = clampA(a.z) - v.z;
        float x3 = clampA(a.w) - v.w;
        x[4 * k + 0] = x0; x[4 * k + 1] = x1;
        x[4 * k + 2] = x2; x[4 * k + 3] = x3;
        mx = fmaxf(mx, fmaxf(fmaxf(x0, x1), fmaxf(x2, x3)));
    }
#pragma unroll
    for (int o = 16; o > 0; o >>= 1)
        mx = fmaxf(mx, __shfl_xor_sync(0xFFFFFFFFu, mx, o));

    __shared__ float rm[4][2];
    __shared__ float rs[4][2];
    if (lane == 0) rm[rl][half] = mx;
    __syncthreads();
    mx = fmaxf(rm[rl][0], rm[rl][1]);

    float s = 0.0f;
#pragma unroll
    for (int k = 0; k < 16; k++)
        s += __expf(x[k] - mx);
#pragma unroll
    for (int o = 16; o > 0; o >>= 1)
        s += __shfl_xor_sync(0xFFFFFFFFu, s, o);
    if (lane == 0) rs[rl][half] = s;
    __syncthreads();

    if (tr == 0)
        g_u[r] = mx + __logf(rs[rl][0] + rs[rl][1]);
}

// ---------------------------------------------------------------------------
// Col pass, stage 1: per-tile partial (m, s) for each column.
// Tile = 64 cols x 128 rows. Block 256 = (16 float4-cols x 16 row-groups).
// Each thread: 8 float4 loads (rows ty+16k), 4 columns, register-resident.
// Batches processed in DESCENDING order (L2 ping-pong with the row pass).
// ---------------------------------------------------------------------------
__global__ void __launch_bounds__(256) col_lse_partial_kernel(const float* __restrict__ M) {
    int b  = NB - 1 - (int)blockIdx.z;
    int tx = threadIdx.x & 15;          // float4-col within tile
    int ty = threadIdx.x >> 4;          // 0..15 row group
    int j4 = blockIdx.x * 16 + tx;      // global float4 col (0..255)
    int i0 = blockIdx.y * 128;          // row chunk start

    __shared__ float us[128];
    __shared__ float4 smv[16][17];      // per-(ty) per-(tx) partials, padded

    if (threadIdx.x < 128)
        us[threadIdx.x] = g_u[b * N + i0 + threadIdx.x];
    __syncthreads();

    const float4* __restrict__ base = reinterpret_cast<const float4*>(M)
                                      + (size_t)b * N * (N / 4) + j4;

    float4 xv[8];
    float4 mx = make_float4(-1e30f, -1e30f, -1e30f, -1e30f);
#pragma unroll
    for (int k = 0; k < 8; k++) {
        int i = ty + 16 * k;
        float4 a = base[(size_t)(i0 + i) * (N / 4)];
        float u = us[i];
        float4 t;
        t.x = clampA(a.x) - u;
        t.y = clampA(a.y) - u;
        t.z = clampA(a.z) - u;
        t.w = clampA(a.w) - u;
        xv[k] = t;
        mx.x = fmaxf(mx.x, t.x); mx.y = fmaxf(mx.y, t.y);
        mx.z = fmaxf(mx.z, t.z); mx.w = fmaxf(mx.w, t.w);
    }

    smv[ty][tx] = mx;
    __syncthreads();

    // Column max across the 16 row-groups (each thread for its 4 columns)
    float4 MX = smv[0][tx];
#pragma unroll
    for (int k = 1; k < 16; k++) {
        float4 t = smv[k][tx];
        MX.x = fmaxf(MX.x, t.x); MX.y = fmaxf(MX.y, t.y);
        MX.z = fmaxf(MX.z, t.z); MX.w = fmaxf(MX.w, t.w);
    }

    float4 s = make_float4(0.f, 0.f, 0.f, 0.f);
#pragma unroll
    for (int k = 0; k < 8; k++) {
        s.x += __expf(xv[k].x - MX.x);
        s.y += __expf(xv[k].y - MX.y);
        s.z += __expf(xv[k].z - MX.z);
        s.w += __expf(xv[k].w - MX.w);
    }
    __syncthreads();
    smv[ty][tx] = s;
    __syncthreads();

    if (ty == 0) {
        float4 SS = smv[0][tx];
#pragma unroll
        for (int k = 1; k < 16; k++) {
            float4 t = smv[k][tx];
            SS.x += t.x; SS.y += t.y; SS.z += t.z; SS.w += t.w;
        }
        size_t p = ((size_t)b * NCHUNK + blockIdx.y) * (N / 4) + j4;
        reinterpret_cast<float4*>(g_pm)[p] = MX;
        reinterpret_cast<float4*>(g_ps)[p] = SS;
    }
}

// Col pass, stage 2: merge the 8 row-chunk partials into v[b][j].
__global__ void __launch_bounds__(256) col_lse_combine_kernel() {
    int t = blockIdx.x * 256 + threadIdx.x;     // float4 index into [NB][N/4]
    int b = t >> 8;
    int j4 = t & 255;

    float4 m = reinterpret_cast<const float4*>(g_pm)[((size_t)b * NCHUNK) * (N / 4) + j4];
    float4 s = reinterpret_cast<const float4*>(g_ps)[((size_t)b * NCHUNK) * (N / 4) + j4];
#pragma unroll
    for (int c = 1; c < NCHUNK; c++) {
        size_t p = ((size_t)b * NCHUNK + c) * (N / 4) + j4;
        float4 pm = reinterpret_cast<const float4*>(g_pm)[p];
        float4 ps = reinterpret_cast<const float4*>(g_ps)[p];
        float nm;
        nm = fmaxf(m.x, pm.x); s.x = s.x * __expf(m.x - nm) + ps.x * __expf(pm.x - nm); m.x = nm;
        nm = fmaxf(m.y, pm.y); s.y = s.y * __expf(m.y - nm) + ps.y * __expf(pm.y - nm); m.y = nm;
        nm = fmaxf(m.z, pm.z); s.z = s.z * __expf(m.z - nm) + ps.z * __expf(pm.z - nm); m.z = nm;
        nm = fmaxf(m.w, pm.w); s.w = s.w * __expf(m.w - nm) + ps.w * __expf(pm.w - nm); m.w = nm;
    }
    float4 v;
    v.x = m.x + __logf(s.x);
    v.y = m.y + __logf(s.y);
    v.z = m.z + __logf(s.z);
    v.w = m.w + __logf(s.w);
    reinterpret_cast<float4*>(g_v)[t] = v;
}

// ---------------------------------------------------------------------------
// Last col pass fused with output: compute v_j in-block (full column), then
// write exp(x - v_j) from register-resident values. Descending batch order.
// ---------------------------------------------------------------------------
__global__ void __launch_bounds__(1024) col_lse_finalize_kernel(const float* __restrict__ M,
                                                                float* __restrict__ out) {
    int b = NB - 1 - (int)blockIdx.y;
    int cx = threadIdx.x;
    int y  = threadIdx.y;
    int j = blockIdx.x * 32 + cx;

    __shared__ float us[N];
    __shared__ float sm_m[32][33];
    __shared__ float sm_s[32][33];

    us[y * 32 + cx] = g_u[b * N + y * 32 + cx];
    __syncthreads();

    const float* __restrict__ base = M + (size_t)b * N * N + j;

    float xv[32];
    float mx = -1e30f;
#pragma unroll
    for (int k = 0; k < 32; k++) {
        int i = y + 32 * k;
        float a = base[(size_t)i * N];
        float t = clampA(a) - us[i];
        xv[k] = t;
        mx = fmaxf(mx, t);
    }

    sm_m[y][cx] = mx;
    __syncthreads();

    float MX = sm_m[0][cx];
#pragma unroll
    for (int k = 1; k < 32; k++)
        MX = fmaxf(MX, sm_m[k][cx]);

    float s = 0.0f;
#pragma unroll
    for (int k = 0; k < 32; k++)
        s += __expf(xv[k] - MX);

    sm_s[y][cx] = s;
    __syncthreads();

    float SS = sm_s[0][cx];
#pragma unroll
    for (int k = 1; k < 32; k++)
        SS += sm_s[k][cx];
    float V = MX + __logf(SS);

    float* __restrict__ obase = out + (size_t)b * N * N + j;
#pragma unroll
    for (int k = 0; k < 32; k++) {
        int i = y + 32 * k;
        obase[(size_t)i * N] = __expf(xv[k] - V);
    }
}

extern "C" void kernel_launch(void* const* d_in, const int* in_sizes, int n_in,
                              void* d_out, int out_size) {
    const float* M = (const float*)d_in[0];
    float* out = (float*)d_out;

    init_v_kernel<<<(NB * N + 255) / 256, 256>>>();

    for (int it = 0; it < ITERS; it++) {
        row_lse_kernel<<<(NB * N) / 4, 256>>>(M);
        if (it < ITERS - 1) {
            col_lse_partial_kernel<<<dim3(N / 64, NCHUNK, NB), 256>>>(M);
            col_lse_combine_kernel<<<(NB * N / 4) / 256, 256>>>();
        } else {
            col_lse_finalize_kernel<<<dim3(N / 32, NB), dim3(32, 32)>>>(M, out);
        }
    }
}